// round 1
// baseline (speedup 1.0000x reference)
#include <cuda_runtime.h>
#include <math.h>

#define B 64
#define R 196
#define L 512
#define K 768
#define NEGF (-2147483647.0f)

// Scratch (no cudaMalloc allowed)
__device__ float g_c[B * R];        // 1 + tanh(image proj)
__device__ float g_q[B * L];        // tanh(seq proj)
__device__ float g_w[B * L];        // q @ V
__device__ float g_S[(size_t)B * R * L]; // softmax probs (pre-scaled by 1/(Z*sqrt(K)))

// ---------------------------------------------------------------------------
// Kernel 1: c[b,r] = 1 + tanh(image_emb[b,r,:] . image_W + image_b)
// one warp per row (B*R = 12544 rows, 512-length dot)
// ---------------------------------------------------------------------------
__global__ void k_proj_p(const float* __restrict__ img,
                         const float* __restrict__ W,
                         const float* __restrict__ bias) {
    int warp = (blockIdx.x * blockDim.x + threadIdx.x) >> 5;
    int lane = threadIdx.x & 31;
    if (warp >= B * R) return;
    const float* row = img + (size_t)warp * L;
    float s = 0.f;
#pragma unroll
    for (int i = 0; i < L / 32; i++) {
        int j = lane + 32 * i;
        s += row[j] * W[j];
    }
#pragma unroll
    for (int o = 16; o; o >>= 1) s += __shfl_xor_sync(0xffffffffu, s, o);
    if (lane == 0) g_c[warp] = 1.0f + tanhf(s + bias[0]);
}

// ---------------------------------------------------------------------------
// Kernel 2: q[b,l] = tanh(seq_emb[b,l,:] . seq_W + seq_b)
// one warp per row (B*L = 32768 rows, 768-length dot)
// ---------------------------------------------------------------------------
__global__ void k_proj_q(const float* __restrict__ seq,
                         const float* __restrict__ W,
                         const float* __restrict__ bias) {
    int warp = (blockIdx.x * blockDim.x + threadIdx.x) >> 5;
    int lane = threadIdx.x & 31;
    if (warp >= B * L) return;
    const float* row = seq + (size_t)warp * K;
    float s = 0.f;
#pragma unroll
    for (int i = 0; i < K / 32; i++) {
        int j = lane + 32 * i;
        s += row[j] * W[j];
    }
#pragma unroll
    for (int o = 16; o; o >>= 1) s += __shfl_xor_sync(0xffffffffu, s, o);
    if (lane == 0) g_q[warp] = tanhf(s + bias[0]);
}

// ---------------------------------------------------------------------------
// Kernel 3: w[b,j] = sum_l q[b,l] * V[l,j]
// grid = 64 b * 4 j-tiles of 128; V rows stay hot in L2 across b
// ---------------------------------------------------------------------------
__global__ void k_wgemv(const float* __restrict__ V) {
    int b = blockIdx.x >> 2;
    int j = ((blockIdx.x & 3) << 7) + threadIdx.x;
    __shared__ float qs[L];
    for (int i = threadIdx.x; i < L; i += 128) qs[i] = g_q[b * L + i];
    __syncthreads();
    float acc = 0.f;
#pragma unroll 8
    for (int l = 0; l < L; l++) acc += qs[l] * V[l * L + j];
    g_w[b * L + j] = acc;
}

// ---------------------------------------------------------------------------
// Kernel 4: masked softmax rows.
// S[b,r,j] = softmax_j( mask ? c[b,r]*w[b,j] : NEG ) / sqrt(K)
// block = 8 warps, one warp per r; w/mask staged in smem per b
// ---------------------------------------------------------------------------
__global__ void k_softmax(const int* __restrict__ mask) {
    int b = blockIdx.x;
    int r = blockIdx.y * 8 + (threadIdx.x >> 5);
    int lane = threadIdx.x & 31;
    __shared__ float ws[L];
    __shared__ int ms[L];
    for (int i = threadIdx.x; i < L; i += 256) {
        ws[i] = g_w[b * L + i];
        ms[i] = mask[b * L + i];
    }
    __syncthreads();
    if (r >= R) return;
    float c = g_c[b * R + r];
    float v[L / 32];
    float m = -INFINITY;
#pragma unroll
    for (int i = 0; i < L / 32; i++) {
        int j = lane + 32 * i;
        v[i] = ms[j] ? c * ws[j] : NEGF;
        m = fmaxf(m, v[i]);
    }
#pragma unroll
    for (int o = 16; o; o >>= 1) m = fmaxf(m, __shfl_xor_sync(0xffffffffu, m, o));
    float z = 0.f;
#pragma unroll
    for (int i = 0; i < L / 32; i++) {
        v[i] = __expf(v[i] - m);
        z += v[i];
    }
#pragma unroll
    for (int o = 16; o; o >>= 1) z += __shfl_xor_sync(0xffffffffu, z, o);
    float inv = 1.0f / (z * 27.712812921102035f); // fold 1/sqrt(768)
    float* Srow = g_S + ((size_t)(b * R + r)) * L;
#pragma unroll
    for (int i = 0; i < L / 32; i++) Srow[lane + 32 * i] = v[i] * inv;
}

// ---------------------------------------------------------------------------
// Kernel 5: out[b] = S[b] (196x512) @ seq_emb[b] (512x768)
// BM=128, BN=128, BK=16, 256 threads, 8x8 microtile per thread
// ---------------------------------------------------------------------------
#define BM 128
#define BN 128
#define BK 16

__global__ __launch_bounds__(256) void k_gemm(const float* __restrict__ E,
                                              float* __restrict__ out) {
    const int b = blockIdx.z;
    const int m0 = blockIdx.y * BM;
    const int n0 = blockIdx.x * BN;
    const float* Sb = g_S + (size_t)b * R * L;
    const float* Eb = E + (size_t)b * L * K;
    float* Ob = out + (size_t)b * R * K;

    __shared__ __align__(16) float As[BK][BM + 4]; // transposed A tile, padded
    __shared__ __align__(16) float Bs[BK][BN];

    const int tx = threadIdx.x & 15;   // n micro index
    const int ty = threadIdx.x >> 4;   // m micro index

    float acc[8][8];
#pragma unroll
    for (int i = 0; i < 8; i++)
#pragma unroll
        for (int j = 0; j < 8; j++) acc[i][j] = 0.f;

    for (int k0 = 0; k0 < L; k0 += BK) {
        // Load A tile: S rows m0..m0+127, cols k0..k0+15 (512 float4s)
#pragma unroll
        for (int i = 0; i < 2; i++) {
            int idx = threadIdx.x + i * 256;
            int row = idx >> 2;
            int c4 = idx & 3;
            int gm = m0 + row;
            float4 v = make_float4(0.f, 0.f, 0.f, 0.f);
            if (gm < R) v = *(const float4*)&Sb[(size_t)gm * L + k0 + c4 * 4];
            As[c4 * 4 + 0][row] = v.x;
            As[c4 * 4 + 1][row] = v.y;
            As[c4 * 4 + 2][row] = v.z;
            As[c4 * 4 + 3][row] = v.w;
        }
        // Load B tile: E rows k0..k0+15, cols n0..n0+127 (512 float4s)
#pragma unroll
        for (int i = 0; i < 2; i++) {
            int idx = threadIdx.x + i * 256;
            int row = idx >> 5;
            int c4 = idx & 31;
            *(float4*)&Bs[row][c4 * 4] =
                *(const float4*)&Eb[(size_t)(k0 + row) * K + n0 + c4 * 4];
        }
        __syncthreads();
#pragma unroll
        for (int kk = 0; kk < BK; kk++) {
            float a[8], bb[8];
            *(float4*)(a) = *(const float4*)&As[kk][ty * 8];
            *(float4*)(a + 4) = *(const float4*)&As[kk][ty * 8 + 4];
            *(float4*)(bb) = *(const float4*)&Bs[kk][tx * 8];
            *(float4*)(bb + 4) = *(const float4*)&Bs[kk][tx * 8 + 4];
#pragma unroll
            for (int i = 0; i < 8; i++)
#pragma unroll
                for (int j = 0; j < 8; j++) acc[i][j] = fmaf(a[i], bb[j], acc[i][j]);
        }
        __syncthreads();
    }

#pragma unroll
    for (int i = 0; i < 8; i++) {
        int gm = m0 + ty * 8 + i;
        if (gm < R) {
            float4 v0 = make_float4(acc[i][0], acc[i][1], acc[i][2], acc[i][3]);
            float4 v1 = make_float4(acc[i][4], acc[i][5], acc[i][6], acc[i][7]);
            *(float4*)&Ob[(size_t)gm * K + n0 + tx * 8] = v0;
            *(float4*)&Ob[(size_t)gm * K + n0 + tx * 8 + 4] = v1;
        }
    }
}

// ---------------------------------------------------------------------------
extern "C" void kernel_launch(void* const* d_in, const int* in_sizes, int n_in,
                              void* d_out, int out_size) {
    const float* image_emb = (const float*)d_in[0]; // [B,R,L]
    const float* seq_emb   = (const float*)d_in[1]; // [B,L,K]
    const int*   mask      = (const int*)d_in[2];   // [B,L]
    const float* image_W   = (const float*)d_in[3]; // [L,1]
    const float* image_b   = (const float*)d_in[4]; // [1]
    const float* seq_W     = (const float*)d_in[5]; // [K,1]
    const float* seq_b     = (const float*)d_in[6]; // [1]
    const float* V_weight  = (const float*)d_in[7]; // [L,L]
    float* out = (float*)d_out;                     // [B,R,K]

    // 1) p projection: B*R rows, 8 warps per block
    k_proj_p<<<(B * R + 7) / 8, 256>>>(image_emb, image_W, image_b);
    // 2) q projection: B*L rows
    k_proj_q<<<(B * L + 7) / 8, 256>>>(seq_emb, seq_W, seq_b);
    // 3) w = q @ V
    k_wgemv<<<B * 4, 128>>>(V_weight);
    // 4) softmax -> S
    k_softmax<<<dim3(B, (R + 7) / 8), 256>>>(mask);
    // 5) out = S @ seq_emb (scaled)
    k_gemm<<<dim3(K / BN, (R + BM - 1) / BM, B), 256>>>(seq_emb, out);
}

// round 2
// speedup vs baseline: 2.1693x; 2.1693x over previous
#include <cuda_runtime.h>
#include <math.h>
#include <stdint.h>

#define B 64
#define R 196
#define L 512
#define K 768
#define NEGF (-2147483647.0f)

// Scratch (no cudaMalloc allowed)
__device__ float g_c[B * R];        // 1 + tanh(image proj)
__device__ float g_q[B * L];        // tanh(seq proj)
__device__ float g_w[B * L];        // q @ V
__device__ float g_S[(size_t)B * R * L]; // softmax probs (pre-scaled by 1/(Z*sqrt(K)))

// ---------------------------------------------------------------------------
// Kernel 1: c[b,r] = 1 + tanh(image_emb[b,r,:] . image_W + image_b)
// ---------------------------------------------------------------------------
__global__ void k_proj_p(const float* __restrict__ img,
                         const float* __restrict__ W,
                         const float* __restrict__ bias) {
    int warp = (blockIdx.x * blockDim.x + threadIdx.x) >> 5;
    int lane = threadIdx.x & 31;
    if (warp >= B * R) return;
    const float* row = img + (size_t)warp * L;
    float s = 0.f;
#pragma unroll
    for (int i = 0; i < L / 32; i++) {
        int j = lane + 32 * i;
        s += row[j] * W[j];
    }
#pragma unroll
    for (int o = 16; o; o >>= 1) s += __shfl_xor_sync(0xffffffffu, s, o);
    if (lane == 0) g_c[warp] = 1.0f + tanhf(s + bias[0]);
}

// ---------------------------------------------------------------------------
// Kernel 2: q[b,l] = tanh(seq_emb[b,l,:] . seq_W + seq_b)
// ---------------------------------------------------------------------------
__global__ void k_proj_q(const float* __restrict__ seq,
                         const float* __restrict__ W,
                         const float* __restrict__ bias) {
    int warp = (blockIdx.x * blockDim.x + threadIdx.x) >> 5;
    int lane = threadIdx.x & 31;
    if (warp >= B * L) return;
    const float* row = seq + (size_t)warp * K;
    float s = 0.f;
#pragma unroll
    for (int i = 0; i < K / 32; i++) {
        int j = lane + 32 * i;
        s += row[j] * W[j];
    }
#pragma unroll
    for (int o = 16; o; o >>= 1) s += __shfl_xor_sync(0xffffffffu, s, o);
    if (lane == 0) g_q[warp] = tanhf(s + bias[0]);
}

// ---------------------------------------------------------------------------
// Kernel 3: w[b,j] = sum_l q[b,l] * V[l,j]
// ---------------------------------------------------------------------------
__global__ void k_wgemv(const float* __restrict__ V) {
    int b = blockIdx.x >> 2;
    int j = ((blockIdx.x & 3) << 7) + threadIdx.x;
    __shared__ float qs[L];
    for (int i = threadIdx.x; i < L; i += 128) qs[i] = g_q[b * L + i];
    __syncthreads();
    float acc = 0.f;
#pragma unroll 8
    for (int l = 0; l < L; l++) acc += qs[l] * V[l * L + j];
    g_w[b * L + j] = acc;
}

// ---------------------------------------------------------------------------
// Kernel 4: masked softmax rows -> g_S (scaled by 1/(Z*sqrt(K)))
// ---------------------------------------------------------------------------
__global__ void k_softmax(const int* __restrict__ mask) {
    int b = blockIdx.x;
    int r = blockIdx.y * 8 + (threadIdx.x >> 5);
    int lane = threadIdx.x & 31;
    __shared__ float ws[L];
    __shared__ int ms[L];
    for (int i = threadIdx.x; i < L; i += 256) {
        ws[i] = g_w[b * L + i];
        ms[i] = mask[b * L + i];
    }
    __syncthreads();
    if (r >= R) return;
    float c = g_c[b * R + r];
    float v[L / 32];
    float m = -INFINITY;
#pragma unroll
    for (int i = 0; i < L / 32; i++) {
        int j = lane + 32 * i;
        v[i] = ms[j] ? c * ws[j] : NEGF;
        m = fmaxf(m, v[i]);
    }
#pragma unroll
    for (int o = 16; o; o >>= 1) m = fmaxf(m, __shfl_xor_sync(0xffffffffu, m, o));
    float z = 0.f;
#pragma unroll
    for (int i = 0; i < L / 32; i++) {
        v[i] = __expf(v[i] - m);
        z += v[i];
    }
#pragma unroll
    for (int o = 16; o; o >>= 1) z += __shfl_xor_sync(0xffffffffu, z, o);
    float inv = 1.0f / (z * 27.712812921102035f); // fold 1/sqrt(768)
    float* Srow = g_S + ((size_t)(b * R + r)) * L;
#pragma unroll
    for (int i = 0; i < L / 32; i++) Srow[lane + 32 * i] = v[i] * inv;
}

// ---------------------------------------------------------------------------
// Kernel 5: out[b] = S[b] (196x512) @ seq_emb[b] (512x768), tf32 tensor cores.
// BM=128, BN=128, BK=32; 8 warps = 4(M) x 2(N); warp tile 32x64.
// Per warp: 2 m16-tiles x 8 n8-tiles, k in steps of 8 (mma.m16n8k8.tf32).
// fp32 -> tf32 (cvt.rna) done once at the gmem->smem stage.
// SMEM strides: A=36 (bank = 4*row+col, conflict-free), B=136 (bank = 8*row+col).
// ---------------------------------------------------------------------------
#define BM 128
#define BN 128
#define BK 32
#define ASTR 36
#define BSTR 136

__device__ __forceinline__ uint32_t f2tf32(float v) {
    uint32_t r;
    asm("cvt.rna.tf32.f32 %0, %1;" : "=r"(r) : "f"(v));
    return r;
}

__global__ __launch_bounds__(256) void k_gemm_tf32(const float* __restrict__ E,
                                                   float* __restrict__ out) {
    const int b = blockIdx.z;
    const int m0 = blockIdx.y * BM;
    const int n0 = blockIdx.x * BN;
    const float* Sb = g_S + (size_t)b * R * L;
    const float* Eb = E + (size_t)b * L * K;
    float* Ob = out + (size_t)b * R * K;

    __shared__ __align__(16) uint32_t As[BM * ASTR];
    __shared__ __align__(16) uint32_t Bs[BK * BSTR];

    const int tid = threadIdx.x;
    const int wid = tid >> 5;
    const int lane = tid & 31;
    const int warp_m = (wid & 3) * 32;
    const int warp_n = (wid >> 2) * 64;
    const int lq = lane >> 2;   // 0..7
    const int lr = lane & 3;    // 0..3

    float acc[2][8][4];
#pragma unroll
    for (int i = 0; i < 2; i++)
#pragma unroll
        for (int j = 0; j < 8; j++)
#pragma unroll
            for (int k = 0; k < 4; k++) acc[i][j][k] = 0.f;

    for (int k0 = 0; k0 < L; k0 += BK) {
        // ---- Load + convert A tile: S[m0..m0+127][k0..k0+31] ----
#pragma unroll
        for (int i = 0; i < 4; i++) {
            int idx = tid + i * 256;          // 0..1023 float4 slots
            int row = idx >> 3;               // 0..127
            int c4 = idx & 7;                 // 8 float4 per row
            int gm = m0 + row;
            float4 v = make_float4(0.f, 0.f, 0.f, 0.f);
            if (gm < R) v = *(const float4*)&Sb[(size_t)gm * L + k0 + c4 * 4];
            uint32_t* dst = &As[row * ASTR + c4 * 4];
            dst[0] = f2tf32(v.x);
            dst[1] = f2tf32(v.y);
            dst[2] = f2tf32(v.z);
            dst[3] = f2tf32(v.w);
        }
        // ---- Load + convert B tile: E[k0..k0+31][n0..n0+127] ----
#pragma unroll
        for (int i = 0; i < 4; i++) {
            int idx = tid + i * 256;          // 0..1023
            int row = idx >> 5;               // 0..31
            int c4 = idx & 31;                // 32 float4 per row
            float4 v = *(const float4*)&Eb[(size_t)(k0 + row) * K + n0 + c4 * 4];
            uint32_t* dst = &Bs[row * BSTR + c4 * 4];
            dst[0] = f2tf32(v.x);
            dst[1] = f2tf32(v.y);
            dst[2] = f2tf32(v.z);
            dst[3] = f2tf32(v.w);
        }
        __syncthreads();

#pragma unroll
        for (int ks = 0; ks < BK / 8; ks++) {
            // A fragments: 2 m16-tiles
            uint32_t af[2][4];
#pragma unroll
            for (int mi = 0; mi < 2; mi++) {
                int row = warp_m + mi * 16 + lq;
                int col = ks * 8 + lr;
                af[mi][0] = As[row * ASTR + col];
                af[mi][1] = As[(row + 8) * ASTR + col];
                af[mi][2] = As[row * ASTR + col + 4];
                af[mi][3] = As[(row + 8) * ASTR + col + 4];
            }
            // B fragments: 8 n8-tiles
            uint32_t bf[8][2];
#pragma unroll
            for (int ni = 0; ni < 8; ni++) {
                int col = warp_n + ni * 8 + lq;
                bf[ni][0] = Bs[(ks * 8 + lr) * BSTR + col];
                bf[ni][1] = Bs[(ks * 8 + 4 + lr) * BSTR + col];
            }
#pragma unroll
            for (int mi = 0; mi < 2; mi++)
#pragma unroll
                for (int ni = 0; ni < 8; ni++) {
                    asm volatile(
                        "mma.sync.aligned.m16n8k8.row.col.f32.tf32.tf32.f32 "
                        "{%0,%1,%2,%3}, {%4,%5,%6,%7}, {%8,%9}, {%0,%1,%2,%3};"
                        : "+f"(acc[mi][ni][0]), "+f"(acc[mi][ni][1]),
                          "+f"(acc[mi][ni][2]), "+f"(acc[mi][ni][3])
                        : "r"(af[mi][0]), "r"(af[mi][1]), "r"(af[mi][2]), "r"(af[mi][3]),
                          "r"(bf[ni][0]), "r"(bf[ni][1]));
                }
        }
        __syncthreads();
    }

    // ---- Epilogue: C layout m16n8 -> rows lq, lq+8; cols 2*lr, 2*lr+1 ----
#pragma unroll
    for (int mi = 0; mi < 2; mi++) {
#pragma unroll
        for (int ni = 0; ni < 8; ni++) {
            int gn = n0 + warp_n + ni * 8 + 2 * lr;
            int gm0 = m0 + warp_m + mi * 16 + lq;
            if (gm0 < R) {
                float2 v = make_float2(acc[mi][ni][0], acc[mi][ni][1]);
                *(float2*)&Ob[(size_t)gm0 * K + gn] = v;
            }
            int gm1 = gm0 + 8;
            if (gm1 < R) {
                float2 v = make_float2(acc[mi][ni][2], acc[mi][ni][3]);
                *(float2*)&Ob[(size_t)gm1 * K + gn] = v;
            }
        }
    }
}

// ---------------------------------------------------------------------------
extern "C" void kernel_launch(void* const* d_in, const int* in_sizes, int n_in,
                              void* d_out, int out_size) {
    const float* image_emb = (const float*)d_in[0]; // [B,R,L]
    const float* seq_emb   = (const float*)d_in[1]; // [B,L,K]
    const int*   mask      = (const int*)d_in[2];   // [B,L]
    const float* image_W   = (const float*)d_in[3]; // [L,1]
    const float* image_b   = (const float*)d_in[4]; // [1]
    const float* seq_W     = (const float*)d_in[5]; // [K,1]
    const float* seq_b     = (const float*)d_in[6]; // [1]
    const float* V_weight  = (const float*)d_in[7]; // [L,L]
    float* out = (float*)d_out;                     // [B,R,K]

    k_proj_p<<<(B * R + 7) / 8, 256>>>(image_emb, image_W, image_b);
    k_proj_q<<<(B * L + 7) / 8, 256>>>(seq_emb, seq_W, seq_b);
    k_wgemv<<<B * 4, 128>>>(V_weight);
    k_softmax<<<dim3(B, (R + 7) / 8), 256>>>(mask);
    k_gemm_tf32<<<dim3(K / BN, (R + BM - 1) / BM, B), 256>>>(seq_emb, out);
}